// round 17
// baseline (speedup 1.0000x reference)
#include <cuda_runtime.h>
#include <cuda_bf16.h>
#include <cstdint>

// Problem constants (fixed by the reference generator).
#define NN   4096      // nodes
#define BB   2048      // batch
#define LL   128       // latent
#define KK   16        // max fan-in
#define DW   145       // 1 + LL + KK  (weights row length)
#define GKK  129       // 1 + LL       (GEMM K dim)

#define NE      14     // batch elements per CTA (147 CTAs -> one wave)
#define STRIDE  4097   // per-element smem stride: bank = (el + p) mod 32
#define PAD     40     // meta/pre pad rows

#define CH      4      // nodes per chunk
#define NCH     1024   // chunks (4*1024 = 4096 exactly)
#define SCALE   2.885390082f   // 2*log2(e): tanh via ex2 without extra FMUL

#define STATE_F (NE * STRIDE)        // 57,358 floats of chain state
#define META_F  (STATE_F + 2)        // 3 bufs x 128 floats (4 nodes x 128B)
#define PREW_F  (META_F + 3 * 128)   // 3 bufs x 64 floats (4 x [14 pre, w1, 0])
#define SMEM_CHAIN_BYTES ((PREW_F + 3 * 64 + 4) * 4)   // 231,760 B <= 232,448

// ---------------------------------------------------------------------------
// Scratch (__device__ globals zero-initialized at load; rows >= NN never
// written -> clamped/overrun reads return zeros; all writes idempotent).
// ---------------------------------------------------------------------------
__device__ float        g_pre[(NN + PAD) * BB];   // pre[i*BB+b], PRE-SCALED
__device__ unsigned int g_meta[(NN + PAD) * 32];  // 16 parent idx + 16 scaled-w
__device__ float        g_w1[NN + PAD];           // scaled sum of w, parent==i-1

// ---------------------------------------------------------------------------
// Kernel 0: probe (shifts ncu's -s 5 capture slot toward chain_kernel).
// ---------------------------------------------------------------------------
__global__ void probe_kernel()
{
    if (threadIdx.x == 0) g_pre[(size_t)(NN + PAD) * BB - 1] = 0.0f;
}

// ---------------------------------------------------------------------------
// Kernel 1: pack per-node metadata (128B line: 16 parents + 16 SCALED
// weights) and w1[i] = scaled sum of weights whose live parent == i-1.
// ---------------------------------------------------------------------------
__global__ void pack_meta_kernel(const float* __restrict__ w,
                                 const int*   __restrict__ par,
                                 const float* __restrict__ mask)
{
    const int wid = threadIdx.x >> 5;
    const int k   = threadIdx.x & 31;
    const int i   = blockIdx.x * 8 + wid;
    if (i >= NN) return;

    float pw = 0.0f;
    if (k < 16) {
        int   p  = par[i * KK + k];
        float wk = w[i * DW + (1 + LL) + k] * SCALE;
        g_meta[i * 32 + k]      = (unsigned)p;
        g_meta[i * 32 + 16 + k] = __float_as_uint(wk);
        if (mask[i * KK + k] != 0.0f && p == i - 1) pw = wk;
    }
    #pragma unroll
    for (int off = 8; off > 0; off >>= 1)
        pw += __shfl_down_sync(0xffffffffu, pw, off);
    if (k == 0) g_w1[i] = pw;
}

// ---------------------------------------------------------------------------
// Kernel 2: pre[i][b] = SCALE * sum_k w[i][k]*base[b][k],  base=[1, z].
// ---------------------------------------------------------------------------
#define G_PAD 68
__global__ void gemm_pre_kernel(const float* __restrict__ z,
                                const float* __restrict__ w)
{
    extern __shared__ float smg[];
    float* As = smg;
    float* Zs = smg + GKK * G_PAD;

    const int i0 = blockIdx.y * 64;
    const int b0 = blockIdx.x * 64;
    const int tid = threadIdx.x;

    for (int idx = tid; idx < 64 * GKK; idx += 256) {
        int r = idx / GKK, k = idx - r * GKK;
        As[k * G_PAD + r] = w[(i0 + r) * DW + k] * SCALE;
    }
    for (int idx = tid; idx < 64 * GKK; idx += 256) {
        int c = idx / GKK, k = idx - c * GKK;
        Zs[k * G_PAD + c] = (k == 0) ? 1.0f : z[(b0 + c) * LL + (k - 1)];
    }
    __syncthreads();

    const int tx = tid & 15;
    const int ty = tid >> 4;
    const int ri = ty * 4, ci = tx * 4;

    float acc[4][4];
#pragma unroll
    for (int r = 0; r < 4; r++)
#pragma unroll
        for (int c = 0; c < 4; c++) acc[r][c] = 0.0f;

#pragma unroll 3
    for (int k = 0; k < GKK; k++) {
        float4 a  = *reinterpret_cast<const float4*>(&As[k * G_PAD + ri]);
        float4 zc = *reinterpret_cast<const float4*>(&Zs[k * G_PAD + ci]);
        float av[4] = {a.x, a.y, a.z, a.w};
        float zv[4] = {zc.x, zc.y, zc.z, zc.w};
#pragma unroll
        for (int r = 0; r < 4; r++)
#pragma unroll
            for (int c = 0; c < 4; c++)
                acc[r][c] = fmaf(av[r], zv[c], acc[r][c]);
    }

#pragma unroll
    for (int r = 0; r < 4; r++) {
        float4 o = make_float4(acc[r][0], acc[r][1], acc[r][2], acc[r][3]);
        *reinterpret_cast<float4*>(&g_pre[(size_t)(i0 + ri + r) * BB + b0 + ci]) = o;
    }
}

// ---------------------------------------------------------------------------
// Producer helpers (warp 1): register-staged chunk loads / smem stores.
// Per chunk (4 nodes): 32 float4 meta + 64 floats prew ([14 pre, w1, 0] x4).
// ---------------------------------------------------------------------------
__device__ __forceinline__ float prew_load(int node, int slot, int b0)
{
    if (node > NN + PAD - 1) node = NN + PAD - 1;
    if (slot < 14) {
        int b = b0 + slot; if (b >= BB) b = BB - 1;
        return __ldg(&g_pre[(size_t)node * BB + b]);
    }
    if (slot == 14) return __ldg(&g_w1[node]);
    return 0.0f;
}

__device__ __forceinline__ void prod_ldg4(int c, int b0, int lane,
                                          float4& m, float& p0, float& p1)
{
    const int base = c * CH;
    int node = base + (lane >> 3);
    if (node > NN + PAD - 1) node = NN + PAD - 1;
    m  = __ldg(reinterpret_cast<const float4*>(g_meta) + (size_t)node * 8 + (lane & 7));
    p0 = prew_load(base + (lane >> 4),     lane & 15, b0);
    p1 = prew_load(base + (lane >> 4) + 2, lane & 15, b0);
}

__device__ __forceinline__ void prod_sts4(float* sm, int c, int lane,
                                          float4 m, float p0, float p1)
{
    const int buf = c % 3;
    reinterpret_cast<float4*>(sm + META_F)[buf * 32 + lane] = m;
    sm[PREW_F + buf * 64 + lane]      = p0;
    sm[PREW_F + buf * 64 + lane + 32] = p1;
}

// ---------------------------------------------------------------------------
// Kernel 3: serial chain, 64 threads, single-buffered pipeline.
// Body m:  (P/W/pre/w1 for node m+1 already in regs from last body)
//   1. 16 LDS gathers for node m+1 (BEFORE u[m] store; stale slot -> 0)
//   2. refill P <- node m+2 (regs just freed; consumed next body)
//   3. tanh for node m (acc built last body) -- MUFU latency hides gathers
//   4. STS u[m]
//   5. 16 FMAs for node m+1 into the alternate acc set (init pre[m+1])
//   6. refill W/pre/w1 <- node m+2
// Only serial chain: t_{m-1} -> w1-patch -> tanh -> t_m (~48 cyc/node).
// Producer (warp 1): register-pipelined 2 phases deep, triple smem buffer.
// ---------------------------------------------------------------------------
__global__ void __launch_bounds__(64, 1)
chain_kernel(float* __restrict__ out)
{
    extern __shared__ float sm[];
    const int tid  = threadIdx.x;
    const int warp = tid >> 5;
    const int lane = tid & 31;
    const int b0   = blockIdx.x * NE;

    for (int j = tid; j < STATE_F; j += 64) sm[j] = 0.0f;
    __syncthreads();

    // Producer prologue: fill buffers 0..2, preload reg set B (= chunk 3).
    float4 mA, mB; float pA0 = 0.f, pA1 = 0.f, pB0 = 0.f, pB1 = 0.f;
    if (warp == 1) {
        for (int cc = 0; cc < 3; cc++) {
            prod_ldg4(cc, b0, lane, mA, pA0, pA1);
            prod_sts4(sm, cc, lane, mA, pA0, pA1);
        }
        prod_ldg4(3, b0, lane, mB, pB0, pB1);
    }
    __syncthreads();

    if (warp == 0) {
        // ------------------------------ consumer ---------------------------
        const int  elc = lane < 14 ? lane : 13;    // lanes 14-31 mirror el 13
        const bool so  = (lane < 14);
        float* __restrict__ u = sm + elc * STRIDE;
        const float4* metaR = reinterpret_cast<const float4*>(sm + META_F);

        int4   P0, P1, P2, P3;                      // parents of node m+1
        float4 W0, W1, W2, W3;                      // weights of node m+1
        float  pre_nxt, w1_cur, w1_nxt;
        float  aA0, aA1, aA2, aA3, aB0, aB1, aB2, aB3;
        float  t1 = 0.0f;

        // Prologue: node 1 meta (buf0 slot1); node 0 acc = {pre[0],0,0,0}.
        {
            const float4* s1 = metaR + 8;           // buf0, slot1
            float4 v;
            v = s1[0]; P0 = make_int4(__float_as_int(v.x), __float_as_int(v.y),
                                      __float_as_int(v.z), __float_as_int(v.w));
            v = s1[1]; P1 = make_int4(__float_as_int(v.x), __float_as_int(v.y),
                                      __float_as_int(v.z), __float_as_int(v.w));
            v = s1[2]; P2 = make_int4(__float_as_int(v.x), __float_as_int(v.y),
                                      __float_as_int(v.z), __float_as_int(v.w));
            v = s1[3]; P3 = make_int4(__float_as_int(v.x), __float_as_int(v.y),
                                      __float_as_int(v.z), __float_as_int(v.w));
            W0 = s1[4]; W1 = s1[5]; W2 = s1[6]; W3 = s1[7];
            pre_nxt = sm[PREW_F + 16 + elc];        // pre[1]
            w1_nxt  = sm[PREW_F + 16 + 14];         // w1[1]
            aA0 = sm[PREW_F + elc];                 // s_0 = pre[0]
            aA1 = 0.f; aA2 = 0.f; aA3 = 0.f;
            w1_cur = sm[PREW_F + 14];               // w1[0] (x0, harmless)
            aB0 = aB1 = aB2 = aB3 = 0.f;
        }

// BODY(J, RB, RS, IN0,IN1,IN2,IN3, OUT0,OUT1,OUT2,OUT3):
//   node m = 4c+J; refill node m+2 from buffer RB slot RS.
#define BODY(J, RB, RS, IN0, IN1, IN2, IN3, OUT0, OUT1, OUT2, OUT3)           \
        {                                                                     \
            /* 1. gathers for node m+1 (before u[m] store) */                 \
            float g0  = u[P0.x], g1  = u[P0.y], g2  = u[P0.z], g3  = u[P0.w]; \
            float g4  = u[P1.x], g5  = u[P1.y], g6  = u[P1.z], g7  = u[P1.w]; \
            float g8  = u[P2.x], g9  = u[P2.y], g10 = u[P2.z], g11 = u[P2.w]; \
            float g12 = u[P3.x], g13 = u[P3.y], g14 = u[P3.z], g15 = u[P3.w]; \
            /* 2. refill P <- node m+2 */                                     \
            {                                                                 \
                const float4* ps = metaR + (RB) * 32 + (RS) * 8;              \
                float4 v;                                                     \
                v = ps[0]; P0 = make_int4(__float_as_int(v.x),                \
                        __float_as_int(v.y), __float_as_int(v.z),             \
                        __float_as_int(v.w));                                 \
                v = ps[1]; P1 = make_int4(__float_as_int(v.x),                \
                        __float_as_int(v.y), __float_as_int(v.z),             \
                        __float_as_int(v.w));                                 \
                v = ps[2]; P2 = make_int4(__float_as_int(v.x),                \
                        __float_as_int(v.y), __float_as_int(v.z),             \
                        __float_as_int(v.w));                                 \
                v = ps[3]; P3 = make_int4(__float_as_int(v.x),                \
                        __float_as_int(v.y), __float_as_int(v.z),             \
                        __float_as_int(v.w));                                 \
            }                                                                 \
            /* 3. tanh for node m (acc from last body); hides gather lat */   \
            float s = ((IN0) + (IN1)) + ((IN2) + (IN3));                      \
            s = fmaf(t1, w1_cur, s);                                          \
            float e, r;                                                       \
            asm("ex2.approx.f32 %0, %1;" : "=f"(e) : "f"(s));                 \
            asm("rcp.approx.f32 %0, %1;" : "=f"(r) : "f"(e + 1.0f));          \
            float t = fmaf(-2.0f, r, 1.0f);                                   \
            /* 4. commit */                                                   \
            if (so) u[m + (J)] = t;                                           \
            t1 = t;                                                           \
            /* 5. FMAs for node m+1 into OUT acc */                           \
            OUT0 = fmaf(g0,  W0.x, pre_nxt);                                  \
            OUT1 = g1  * W0.y;                                                \
            OUT2 = g2  * W0.z;                                                \
            OUT3 = g3  * W0.w;                                                \
            OUT0 = fmaf(g4,  W1.x, OUT0);                                     \
            OUT1 = fmaf(g5,  W1.y, OUT1);                                     \
            OUT2 = fmaf(g6,  W1.z, OUT2);                                     \
            OUT3 = fmaf(g7,  W1.w, OUT3);                                     \
            OUT0 = fmaf(g8,  W2.x, OUT0);                                     \
            OUT1 = fmaf(g9,  W2.y, OUT1);                                     \
            OUT2 = fmaf(g10, W2.z, OUT2);                                     \
            OUT3 = fmaf(g11, W2.w, OUT3);                                     \
            OUT0 = fmaf(g12, W3.x, OUT0);                                     \
            OUT1 = fmaf(g13, W3.y, OUT1);                                     \
            OUT2 = fmaf(g14, W3.z, OUT2);                                     \
            OUT3 = fmaf(g15, W3.w, OUT3);                                     \
            /* 6. refill W/pre/w1 <- node m+2; rotate scalars */              \
            {                                                                 \
                const float4* ws = metaR + (RB) * 32 + (RS) * 8;              \
                W0 = ws[4]; W1 = ws[5]; W2 = ws[6]; W3 = ws[7];               \
                w1_cur  = w1_nxt;                                             \
                pre_nxt = sm[PREW_F + (RB) * 64 + (RS) * 16 + elc];           \
                w1_nxt  = sm[PREW_F + (RB) * 64 + (RS) * 16 + 14];            \
            }                                                                 \
        }

#pragma unroll 1
        for (int c = 0; c < NCH; c++) {
            const int cur = c % 3;
            const int nxt = (cur == 2) ? 0 : cur + 1;
            const int m   = c << 2;
            BODY(0, cur, 2, aA0, aA1, aA2, aA3, aB0, aB1, aB2, aB3)
            BODY(1, cur, 3, aB0, aB1, aB2, aB3, aA0, aA1, aA2, aA3)
            BODY(2, nxt, 0, aA0, aA1, aA2, aA3, aB0, aB1, aB2, aB3)
            BODY(3, nxt, 1, aB0, aB1, aB2, aB3, aA0, aA1, aA2, aA3)
            __syncthreads();                       // phase boundary
        }
#undef BODY
    } else {
        // ------------------------------ producer ---------------------------
#pragma unroll 1
        for (int c = 0; c < NCH; c += 2) {
            if (c > 0) prod_sts4(sm, c + 2, lane, mA, pA0, pA1);
            prod_ldg4(c + 4, b0, lane, mA, pA0, pA1);
            __syncthreads();
            prod_sts4(sm, c + 3, lane, mB, pB0, pB1);
            prod_ldg4(c + 5, b0, lane, mB, pB0, pB1);
            __syncthreads();
        }
    }
    __syncthreads();

    // Coalesced dump: SMEM -> out[b*NN + i] (STG.128).
    for (int e = 0; e < NE; e++) {
        const int b = blockIdx.x * NE + e;
        if (b >= BB) break;
        const float* __restrict__ us = sm + e * STRIDE;
        float4* __restrict__ o4 = reinterpret_cast<float4*>(out + (size_t)b * NN);
        for (int j = tid; j < NN / 4; j += 64) {
            float4 v = make_float4(us[j * 4], us[j * 4 + 1],
                                   us[j * 4 + 2], us[j * 4 + 3]);
            o4[j] = v;
        }
    }
}

// ---------------------------------------------------------------------------
// Launch. Inputs: z f32[2048,128], weights f32[4096,145],
// parent_mask f32[4096,16], parents i32[4096,16]. Output: f32[2048, 4096].
// ---------------------------------------------------------------------------
extern "C" void kernel_launch(void* const* d_in, const int* in_sizes, int n_in,
                              void* d_out, int out_size)
{
    const float* z       = (const float*)d_in[0];
    const float* weights = (const float*)d_in[1];
    const float* pmask   = (const float*)d_in[2];
    const int*   parents = (const int*)d_in[3];
    float*       out     = (float*)d_out;

    const int gemm_smem  = 2 * GKK * G_PAD * (int)sizeof(float);   // 70,176 B
    const int chain_smem = SMEM_CHAIN_BYTES;                        // 231,760 B

    cudaFuncSetAttribute(gemm_pre_kernel,
                         cudaFuncAttributeMaxDynamicSharedMemorySize, gemm_smem);
    cudaFuncSetAttribute(chain_kernel,
                         cudaFuncAttributeMaxDynamicSharedMemorySize, chain_smem);

    probe_kernel<<<1, 32>>>();

    pack_meta_kernel<<<(NN + 7) / 8, 256>>>(weights, parents, pmask);

    dim3 ggrid(BB / 64, NN / 64);
    gemm_pre_kernel<<<ggrid, 256, gemm_smem>>>(z, weights);

    const int nblocks = (BB + NE - 1) / NE;   // 147
    chain_kernel<<<nblocks, 64, chain_smem>>>(out);
}